// round 12
// baseline (speedup 1.0000x reference)
#include <cuda_runtime.h>
#include <stdint.h>

#define BATCH 2048
#define KTOP  32
#define DDIM  768
#define DICT  24576
#define CONN  64

#define FT    64                 // up-feature tile width
#define NFT   (DICT / FT)        // 384 tiles
#define DH    64                 // d-slice size (16.6KB slab -> 8 blocks/SM)
#define NSL   (DDIM / DH)        // 12 slices
#define CAP   256                // max pair records per tile bucket
#define SROW  (FT + 1)           // padded smem row stride (65)

#define NMATCH 2048
#define NK1    3072              // (bid&3)==3 -> bias (768), else match slot

#define NFUSE  (NSL * NFT)       // 4608
#define NEPI   256
#define NK2    4864              // bid%19==18 -> epilogue (256), else fused (4608)

__device__ float    g_bias[DICT];
__device__ unsigned g_bcnt[NFT];     // zeroed by K2 after use (self-maintaining)
__device__ unsigned g_done[NFT];     // arrival counters, self-resetting
// pair record: x = out position (b*K+i), y = down dict idx, z = up dict idx,
//              w = float bits of up_val[j]   (one record PER HIT)
__device__ uint4    g_bpairs[NFT * CAP];

// ---------------------------------------------------------------------------
// K1: match (latency-bound) co-scheduled with bias matvec (DRAM-bound), 3:1.
// ---------------------------------------------------------------------------
__global__ __launch_bounds__(256) void k1_kernel(
    const float* __restrict__ up_vals,        // [B, K]
    const int*   __restrict__ up_indices,     // [B, K]
    const int*   __restrict__ down_indices,   // [B, K]
    const int*   __restrict__ connections,    // [DICT, C]
    const float* __restrict__ up_encoder_w,   // [DICT, D]
    const float* __restrict__ b_dec,          // [D]
    float*       __restrict__ out)            // [B, K]
{
    __shared__ float    s_b[DDIM];            // bias path
    __shared__ int      s_up_idx[KTOP];       // match path
    __shared__ float    s_up_val[KTOP];
    __shared__ int      s_down_idx[KTOP];
    __shared__ unsigned s_bm[DICT / 32];      // 3KB presence bitmap

    const int bid  = blockIdx.x;
    const int t    = threadIdx.x;
    const int warp = t >> 5;
    const int lane = t & 31;

    if ((bid & 3) == 3) {
        // ----------------- bias path: 32 rows, 4 per warp (MLP 24) ---------
        for (int i = t; i < DDIM; i += 256) s_b[i] = b_dec[i];
        __syncthreads();

        const int row0 = (bid >> 2) * 32 + warp * 4;
        const float4* w  = reinterpret_cast<const float4*>(
            up_encoder_w + (size_t)row0 * DDIM);
        const float4* bb = reinterpret_cast<const float4*>(s_b);
        const int RS = DDIM / 4;               // 192
        float a0 = 0.f, a1 = 0.f, a2 = 0.f, a3 = 0.f;
#pragma unroll
        for (int k = 0; k < DDIM / 128; k++) { // 6 iters, 24 indep LDG.128
            int c = lane + 32 * k;
            float4 b  = bb[c];
            float4 v0 = w[0 * RS + c];
            float4 v1 = w[1 * RS + c];
            float4 v2 = w[2 * RS + c];
            float4 v3 = w[3 * RS + c];
            a0 += v0.x * b.x + v0.y * b.y + v0.z * b.z + v0.w * b.w;
            a1 += v1.x * b.x + v1.y * b.y + v1.z * b.z + v1.w * b.w;
            a2 += v2.x * b.x + v2.y * b.y + v2.z * b.z + v2.w * b.w;
            a3 += v3.x * b.x + v3.y * b.y + v3.z * b.z + v3.w * b.w;
        }
#pragma unroll
        for (int o = 16; o > 0; o >>= 1) {
            a0 += __shfl_xor_sync(0xffffffffu, a0, o);
            a1 += __shfl_xor_sync(0xffffffffu, a1, o);
            a2 += __shfl_xor_sync(0xffffffffu, a2, o);
            a3 += __shfl_xor_sync(0xffffffffu, a3, o);
        }
        if (lane == 0) {
            g_bias[row0 + 0] = a0;
            g_bias[row0 + 1] = a1;
            g_bias[row0 + 2] = a2;
            g_bias[row0 + 3] = a3;
        }
        return;
    }

    // ----------------- match path: rare-hit bitmap filter ------------------
    const int b = (bid >> 2) * 3 + (bid & 3);  // 0..2303
    if (b >= NMATCH) return;

#pragma unroll
    for (int r = 0; r < (DICT / 32) / 256; r++)
        s_bm[t + 256 * r] = 0u;

    if (t < KTOP) {
        int ui = up_indices[b * KTOP + t];
        s_up_idx[t]   = ui;
        s_up_val[t]   = up_vals[b * KTOP + t];
        s_down_idx[t] = down_indices[b * KTOP + t];
        out[b * KTOP + t] = 0.f;              // base; everything adds atomically
    }
    __syncthreads();

    if (t < KTOP)
        atomicOr(&s_bm[(unsigned)s_up_idx[t] >> 5], 1u << (s_up_idx[t] & 31));
    __syncthreads();

    // 32 rows x 16 int4 = 512 items streamed through the bitmap.
#pragma unroll
    for (int item = t; item < KTOP * (CONN / 4); item += 256) {
        int i = item >> 4;
        int q = item & 15;
        int di = s_down_idx[i];
        int4 a = reinterpret_cast<const int4*>(connections + (size_t)di * CONN)[q];
        int av[4] = {a.x, a.y, a.z, a.w};
#pragma unroll
        for (int s = 0; s < 4; s++) {
            int v = av[s];
            bool hit = false;
            if (v >= 0)
                hit = (s_bm[(unsigned)v >> 5] >> (v & 31)) & 1u;
            if (hit) {
                // rare (~0.23% of slots): resolve matching j's (handles dups)
                for (int j = 0; j < KTOP; j++) {
                    if (s_up_idx[j] == v) {
                        unsigned pos = atomicAdd(&g_bcnt[(unsigned)v >> 6], 1u);
                        if (pos < CAP) {
                            uint4 rec;
                            rec.x = (unsigned)(b * KTOP + i);
                            rec.y = (unsigned)di;
                            rec.z = (unsigned)v;
                            rec.w = __float_as_uint(s_up_val[j]);
                            g_bpairs[((unsigned)v >> 6) * CAP + pos] = rec;
                        }
                    }
                }
            }
        }
    }
}

// ---------------------------------------------------------------------------
// K2: fused slab dots (DRAM-bound) co-scheduled with bias-gather epilogue
// (latency-bound), 18:1. DH=64 slab -> full occupancy (8 blocks/SM).
// Counter reset: snapshot into smem (stable local copy), then arrive.
// ---------------------------------------------------------------------------
__global__ __launch_bounds__(256) void k2_kernel(
    const float* __restrict__ up_decoder_w,   // [D, DICT]
    const float* __restrict__ down_encoder_w, // [DICT, D]
    const int*   __restrict__ up_indices,     // [B*K]
    float*       __restrict__ out)            // [B*K]
{
    __shared__ float    s[DH * SROW];          // 16,640 B slab
    __shared__ unsigned s_cnt;

    const int bid = blockIdx.x;
    const int t   = threadIdx.x;

    if (bid % 19 == 18) {
        // ----------------- epilogue path: add bias base --------------------
        int i = (bid / 19) * 256 + t;
        atomicAdd(&out[i], g_bias[up_indices[i]]);
        return;
    }

    // ----------------- fused path ------------------------------------------
    const int fidx  = (bid / 19) * 18 + (bid % 19);  // 0..NFUSE-1
    const int tile  = fidx / NSL;
    const int slice = fidx % NSL;

    // Snapshot count into smem (stable), barrier, then signal arrival. The
    // last arriving slice-block resets counters for the next graph replay;
    // s_cnt is untouched by the reset so later readers are safe.
    if (t == 0) s_cnt = g_bcnt[tile];
    __syncthreads();
    const unsigned cnt_raw = s_cnt;
    if (t == 0) {
        unsigned old = atomicAdd(&g_done[tile], 1u);
        if (old == NSL - 1) {
            g_bcnt[tile] = 0u;
            g_done[tile] = 0u;
        }
    }
    const int cnt = (int)(cnt_raw < CAP ? cnt_raw : CAP);
    if (cnt == 0) return;

    const int f0 = tile * FT;
    const int d0 = slice * DH;

    // Load slab: DH x FT = 1024 float4 / 256 threads = 4 each, coalesced.
    const float4* src = reinterpret_cast<const float4*>(
        up_decoder_w + (size_t)d0 * DICT + f0);
    const int RS4 = DICT / 4;
#pragma unroll
    for (int it = 0; it < (DH * FT / 4) / 256; it++) {
        int idx = t + 256 * it;
        int row = idx >> 4;                    // / (FT/4)
        int c4  = idx & 15;
        float4 v = src[(size_t)row * RS4 + c4];
        float* dst = &s[row * SROW + c4 * 4];
        dst[0] = v.x; dst[1] = v.y; dst[2] = v.z; dst[3] = v.w;
    }
    __syncthreads();

    const int warp = t >> 5;
    const int lane = t & 31;
    for (int p = warp; p < cnt; p += 8) {
        uint4 rec = g_bpairs[tile * CAP + p];
        const int fl = (int)rec.z - f0;
        const float* drow = down_encoder_w + (size_t)rec.y * DDIM + d0;
        float acc = 0.f;
#pragma unroll
        for (int m = 0; m < DH / 32; m++) {    // 2 iters, conflict-free smem
            int dd = lane + 32 * m;
            acc += s[dd * SROW + fl] * drow[dd];
        }
#pragma unroll
        for (int o = 16; o > 0; o >>= 1)
            acc += __shfl_xor_sync(0xffffffffu, acc, o);
        if (lane == 0)
            atomicAdd(&out[rec.x], acc * __uint_as_float(rec.w));
    }
}

// ---------------------------------------------------------------------------
extern "C" void kernel_launch(void* const* d_in, const int* in_sizes, int n_in,
                              void* d_out, int out_size)
{
    const float* up_vals        = (const float*)d_in[0];
    const float* up_decoder_w   = (const float*)d_in[1];
    const float* down_encoder_w = (const float*)d_in[2];
    const float* up_encoder_w   = (const float*)d_in[3];
    const float* b_dec          = (const float*)d_in[4];
    const int*   up_indices     = (const int*)d_in[5];
    const int*   down_indices   = (const int*)d_in[6];
    const int*   connections    = (const int*)d_in[7];
    float*       out            = (float*)d_out;

    k1_kernel<<<NK1, 256>>>(up_vals, up_indices, down_indices, connections,
                            up_encoder_w, b_dec, out);
    k2_kernel<<<NK2, 256>>>(up_decoder_w, down_encoder_w, up_indices, out);
}

// round 13
// speedup vs baseline: 1.0435x; 1.0435x over previous
#include <cuda_runtime.h>
#include <stdint.h>

#define BATCH 2048
#define KTOP  32
#define DDIM  768
#define DICT  24576
#define CONN  64

#define FT    64                 // up-feature tile width
#define NFT   (DICT / FT)        // 384 tiles
#define DH    64                 // d-slice size (16.6KB slab -> 8 blocks/SM)
#define NSL   (DDIM / DH)        // 12 slices
#define CAP   256                // max pair records per tile bucket
#define SROW  (FT + 1)           // padded smem row stride (65)

#define NMATCH 2048
#define NK1    3072              // (bid&3)==3 -> bias (768), else match slot

#define NFUSE  (NSL * NFT)       // 4608
#define NEPI   256
#define NK2    4864              // bid%19==18 -> epilogue (256), else fused (4608)

__device__ float    g_bias[DICT];
__device__ unsigned g_bcnt[NFT];     // zeroed by K2 after use (self-maintaining)
__device__ unsigned g_done[NFT];     // arrival counters, self-resetting
// pair record: x = out position (b*K+i), y = down dict idx, z = up dict idx,
//              w = float bits of up_val[j]   (one record PER HIT)
// NOTE: every field ever written is bounded (x < B*K, y/z < DICT), and the
// array is zero-initialized, so SPECULATIVE reads of stale records are safe.
__device__ uint4    g_bpairs[NFT * CAP];

// ---------------------------------------------------------------------------
// K1: match (latency-bound) co-scheduled with bias matvec (DRAM-bound), 3:1.
// ---------------------------------------------------------------------------
__global__ __launch_bounds__(256) void k1_kernel(
    const float* __restrict__ up_vals,        // [B, K]
    const int*   __restrict__ up_indices,     // [B, K]
    const int*   __restrict__ down_indices,   // [B, K]
    const int*   __restrict__ connections,    // [DICT, C]
    const float* __restrict__ up_encoder_w,   // [DICT, D]
    const float* __restrict__ b_dec,          // [D]
    float*       __restrict__ out)            // [B, K]
{
    __shared__ float    s_b[DDIM];            // bias path
    __shared__ int      s_up_idx[KTOP];       // match path
    __shared__ float    s_up_val[KTOP];
    __shared__ int      s_down_idx[KTOP];
    __shared__ unsigned s_bm[DICT / 32];      // 3KB presence bitmap

    const int bid  = blockIdx.x;
    const int t    = threadIdx.x;
    const int warp = t >> 5;
    const int lane = t & 31;

    if ((bid & 3) == 3) {
        // ----------------- bias path: 32 rows, 4 per warp (MLP 24) ---------
        for (int i = t; i < DDIM; i += 256) s_b[i] = b_dec[i];
        __syncthreads();

        const int row0 = (bid >> 2) * 32 + warp * 4;
        const float4* w  = reinterpret_cast<const float4*>(
            up_encoder_w + (size_t)row0 * DDIM);
        const float4* bb = reinterpret_cast<const float4*>(s_b);
        const int RS = DDIM / 4;               // 192
        float a0 = 0.f, a1 = 0.f, a2 = 0.f, a3 = 0.f;
#pragma unroll
        for (int k = 0; k < DDIM / 128; k++) { // 6 iters, 24 indep LDG.128
            int c = lane + 32 * k;
            float4 b  = bb[c];
            float4 v0 = w[0 * RS + c];
            float4 v1 = w[1 * RS + c];
            float4 v2 = w[2 * RS + c];
            float4 v3 = w[3 * RS + c];
            a0 += v0.x * b.x + v0.y * b.y + v0.z * b.z + v0.w * b.w;
            a1 += v1.x * b.x + v1.y * b.y + v1.z * b.z + v1.w * b.w;
            a2 += v2.x * b.x + v2.y * b.y + v2.z * b.z + v2.w * b.w;
            a3 += v3.x * b.x + v3.y * b.y + v3.z * b.z + v3.w * b.w;
        }
#pragma unroll
        for (int o = 16; o > 0; o >>= 1) {
            a0 += __shfl_xor_sync(0xffffffffu, a0, o);
            a1 += __shfl_xor_sync(0xffffffffu, a1, o);
            a2 += __shfl_xor_sync(0xffffffffu, a2, o);
            a3 += __shfl_xor_sync(0xffffffffu, a3, o);
        }
        if (lane == 0) {
            g_bias[row0 + 0] = a0;
            g_bias[row0 + 1] = a1;
            g_bias[row0 + 2] = a2;
            g_bias[row0 + 3] = a3;
        }
        return;
    }

    // ----------------- match path: rare-hit bitmap filter ------------------
    const int b = (bid >> 2) * 3 + (bid & 3);  // 0..2303
    if (b >= NMATCH) return;

#pragma unroll
    for (int r = 0; r < (DICT / 32) / 256; r++)
        s_bm[t + 256 * r] = 0u;

    if (t < KTOP) {
        int ui = up_indices[b * KTOP + t];
        s_up_idx[t]   = ui;
        s_up_val[t]   = up_vals[b * KTOP + t];
        s_down_idx[t] = down_indices[b * KTOP + t];
        out[b * KTOP + t] = 0.f;              // base; everything adds atomically
    }
    __syncthreads();

    if (t < KTOP)
        atomicOr(&s_bm[(unsigned)s_up_idx[t] >> 5], 1u << (s_up_idx[t] & 31));
    __syncthreads();

    // 32 rows x 16 int4 = 512 items streamed through the bitmap.
#pragma unroll
    for (int item = t; item < KTOP * (CONN / 4); item += 256) {
        int i = item >> 4;
        int q = item & 15;
        int di = s_down_idx[i];
        int4 a = reinterpret_cast<const int4*>(connections + (size_t)di * CONN)[q];
        int av[4] = {a.x, a.y, a.z, a.w};
#pragma unroll
        for (int s = 0; s < 4; s++) {
            int v = av[s];
            bool hit = false;
            if (v >= 0)
                hit = (s_bm[(unsigned)v >> 5] >> (v & 31)) & 1u;
            if (hit) {
                // rare (~0.23% of slots): resolve matching j's (handles dups)
                for (int j = 0; j < KTOP; j++) {
                    if (s_up_idx[j] == v) {
                        unsigned pos = atomicAdd(&g_bcnt[(unsigned)v >> 6], 1u);
                        if (pos < CAP) {
                            uint4 rec;
                            rec.x = (unsigned)(b * KTOP + i);
                            rec.y = (unsigned)di;
                            rec.z = (unsigned)v;
                            rec.w = __float_as_uint(s_up_val[j]);
                            g_bpairs[((unsigned)v >> 6) * CAP + pos] = rec;
                        }
                    }
                }
            }
        }
    }
}

// ---------------------------------------------------------------------------
// K2: fused slab dots, software-pipelined. All independent loads (slab, count,
// first record, its drow values) issue up front so the dependent chain hides
// under the slab's DRAM service; post-barrier work is smem + prefetched regs.
// ---------------------------------------------------------------------------
__global__ __launch_bounds__(256) void k2_kernel(
    const float* __restrict__ up_decoder_w,   // [D, DICT]
    const float* __restrict__ down_encoder_w, // [DICT, D]
    const int*   __restrict__ up_indices,     // [B*K]
    float*       __restrict__ out)            // [B*K]
{
    __shared__ float    s[DH * SROW];          // 16,640 B slab
    __shared__ unsigned s_cnt;

    const int bid = blockIdx.x;
    const int t   = threadIdx.x;

    if (bid % 19 == 18) {
        // ----------------- epilogue path: add bias base --------------------
        int i = (bid / 19) * 256 + t;
        atomicAdd(&out[i], g_bias[up_indices[i]]);
        return;
    }

    // ----------------- fused path ------------------------------------------
    const int fidx  = (bid / 19) * 18 + (bid % 19);  // 0..NFUSE-1
    const int tile  = fidx / NSL;
    const int slice = fidx % NSL;
    const int f0 = tile * FT;
    const int d0 = slice * DH;
    const int warp = t >> 5;
    const int lane = t & 31;

    // (1) Issue slab loads first: DH x FT = 1024 float4, 4 per thread.
    const float4* src = reinterpret_cast<const float4*>(
        up_decoder_w + (size_t)d0 * DICT + f0);
    const int RS4 = DICT / 4;
    float4 v0 = src[(size_t)((t + 0) >> 4) * RS4 + ((t + 0) & 15)];
    float4 v1 = src[(size_t)((t + 256) >> 4) * RS4 + ((t + 256) & 15)];
    float4 v2 = src[(size_t)((t + 512) >> 4) * RS4 + ((t + 512) & 15)];
    float4 v3 = src[(size_t)((t + 768) >> 4) * RS4 + ((t + 768) & 15)];

    // (2) Concurrent independent reads: count + speculative first record.
    if (t == 0) s_cnt = g_bcnt[tile];
    uint4 rec0 = g_bpairs[tile * CAP + warp];        // speculative, bounds-safe
    // Dependent drow prefetch for record 0 — hides under slab DRAM service.
    const float* drow0 = down_encoder_w + (size_t)rec0.y * DDIM + d0;
    float dr0a = drow0[lane];
    float dr0b = drow0[lane + 32];

    // (3) Store slab to smem, barrier.
    {
        float* d;
        d = &s[((t + 0) >> 4) * SROW + ((t + 0) & 15) * 4];
        d[0] = v0.x; d[1] = v0.y; d[2] = v0.z; d[3] = v0.w;
        d = &s[((t + 256) >> 4) * SROW + ((t + 256) & 15) * 4];
        d[0] = v1.x; d[1] = v1.y; d[2] = v1.z; d[3] = v1.w;
        d = &s[((t + 512) >> 4) * SROW + ((t + 512) & 15) * 4];
        d[0] = v2.x; d[1] = v2.y; d[2] = v2.z; d[3] = v2.w;
        d = &s[((t + 768) >> 4) * SROW + ((t + 768) & 15) * 4];
        d[0] = v3.x; d[1] = v3.y; d[2] = v3.z; d[3] = v3.w;
    }
    __syncthreads();

    const unsigned cnt_raw = s_cnt;
    // Arrive/reset AFTER the barrier: t0's count value is consumed (in smem),
    // so the last slice-block may safely zero the counters for the next replay.
    if (t == 0) {
        unsigned old = atomicAdd(&g_done[tile], 1u);
        if (old == NSL - 1) {
            g_bcnt[tile] = 0u;
            g_done[tile] = 0u;
        }
    }
    const int cnt = (int)(cnt_raw < CAP ? cnt_raw : CAP);
    if (cnt == 0) return;

    // (4) Record 0: fully prefetched — pure smem + register math.
    if (warp < cnt) {
        const int fl = (int)rec0.z - f0;
        float acc = s[lane * SROW + fl] * dr0a
                  + s[(lane + 32) * SROW + fl] * dr0b;
#pragma unroll
        for (int o = 16; o > 0; o >>= 1)
            acc += __shfl_xor_sync(0xffffffffu, acc, o);
        if (lane == 0)
            atomicAdd(&out[rec0.x], acc * __uint_as_float(rec0.w));
    }

    // Rare extra records (cnt > 8): slow path.
    for (int p = warp + 8; p < cnt; p += 8) {
        uint4 rec = g_bpairs[tile * CAP + p];
        const int fl = (int)rec.z - f0;
        const float* drow = down_encoder_w + (size_t)rec.y * DDIM + d0;
        float acc = s[lane * SROW + fl] * drow[lane]
                  + s[(lane + 32) * SROW + fl] * drow[lane + 32];
#pragma unroll
        for (int o = 16; o > 0; o >>= 1)
            acc += __shfl_xor_sync(0xffffffffu, acc, o);
        if (lane == 0)
            atomicAdd(&out[rec.x], acc * __uint_as_float(rec.w));
    }
}

// ---------------------------------------------------------------------------
extern "C" void kernel_launch(void* const* d_in, const int* in_sizes, int n_in,
                              void* d_out, int out_size)
{
    const float* up_vals        = (const float*)d_in[0];
    const float* up_decoder_w   = (const float*)d_in[1];
    const float* down_encoder_w = (const float*)d_in[2];
    const float* up_encoder_w   = (const float*)d_in[3];
    const float* b_dec          = (const float*)d_in[4];
    const int*   up_indices     = (const int*)d_in[5];
    const int*   down_indices   = (const int*)d_in[6];
    const int*   connections    = (const int*)d_in[7];
    float*       out            = (float*)d_out;

    k1_kernel<<<NK1, 256>>>(up_vals, up_indices, down_indices, connections,
                            up_encoder_w, b_dec, out);
    k2_kernel<<<NK2, 256>>>(up_decoder_w, down_encoder_w, up_indices, out);
}

// round 14
// speedup vs baseline: 1.1614x; 1.1130x over previous
#include <cuda_runtime.h>
#include <stdint.h>

#define BATCH 2048
#define KTOP  32
#define DDIM  768
#define DICT  24576
#define CONN  64

#define FT    64                 // up-feature tile width
#define NFT   (DICT / FT)        // 384 tiles
#define DH    64                 // d-slice size (16.6KB slab -> 8 blocks/SM)
#define NSL   (DDIM / DH)        // 12 slices
#define CAP   256                // max pair records per tile bucket
#define SROW  (FT + 1)           // padded smem row stride (65)

#define NMATCH 2048
#define NK1    3072              // (bid&3)==3 -> bias (768), else match slot

#define NFUSE  (NSL * NFT)       // 4608
#define NEPI   256
#define NK2    4864              // bid%19==18 -> epilogue (256), else fused (4608)

__device__ float    g_bias[DICT];
__device__ unsigned g_bcnt[NFT];     // zeroed by K2 after use (self-maintaining)
__device__ unsigned g_done[NFT];     // arrival counters, self-resetting
// pair record: x = out position (b*K+i), y = down dict idx, z = up dict idx,
//              w = float bits of up_val[j]   (one record PER HIT)
// NOTE: every field ever written is bounded (x < B*K, y/z < DICT), and the
// array is zero-initialized, so SPECULATIVE reads of stale records are safe.
__device__ uint4    g_bpairs[NFT * CAP];

// ---------------------------------------------------------------------------
// K1: match (latency-bound) co-scheduled with bias matvec (DRAM-bound), 3:1.
// Each block fires the PDL trigger when its work (and writes) are complete.
// ---------------------------------------------------------------------------
__global__ __launch_bounds__(256) void k1_kernel(
    const float* __restrict__ up_vals,        // [B, K]
    const int*   __restrict__ up_indices,     // [B, K]
    const int*   __restrict__ down_indices,   // [B, K]
    const int*   __restrict__ connections,    // [DICT, C]
    const float* __restrict__ up_encoder_w,   // [DICT, D]
    const float* __restrict__ b_dec,          // [D]
    float*       __restrict__ out)            // [B, K]
{
    __shared__ float    s_b[DDIM];            // bias path
    __shared__ int      s_up_idx[KTOP];       // match path
    __shared__ float    s_up_val[KTOP];
    __shared__ int      s_down_idx[KTOP];
    __shared__ unsigned s_bm[DICT / 32];      // 3KB presence bitmap

    const int bid  = blockIdx.x;
    const int t    = threadIdx.x;
    const int warp = t >> 5;
    const int lane = t & 31;

    if ((bid & 3) == 3) {
        // ----------------- bias path: 32 rows, 4 per warp (MLP 24) ---------
        for (int i = t; i < DDIM; i += 256) s_b[i] = b_dec[i];
        __syncthreads();

        const int row0 = (bid >> 2) * 32 + warp * 4;
        const float4* w  = reinterpret_cast<const float4*>(
            up_encoder_w + (size_t)row0 * DDIM);
        const float4* bb = reinterpret_cast<const float4*>(s_b);
        const int RS = DDIM / 4;               // 192
        float a0 = 0.f, a1 = 0.f, a2 = 0.f, a3 = 0.f;
#pragma unroll
        for (int k = 0; k < DDIM / 128; k++) { // 6 iters, 24 indep LDG.128
            int c = lane + 32 * k;
            float4 b  = bb[c];
            float4 v0 = __ldcs(&w[0 * RS + c]);   // streaming: no L2 reuse
            float4 v1 = __ldcs(&w[1 * RS + c]);
            float4 v2 = __ldcs(&w[2 * RS + c]);
            float4 v3 = __ldcs(&w[3 * RS + c]);
            a0 += v0.x * b.x + v0.y * b.y + v0.z * b.z + v0.w * b.w;
            a1 += v1.x * b.x + v1.y * b.y + v1.z * b.z + v1.w * b.w;
            a2 += v2.x * b.x + v2.y * b.y + v2.z * b.z + v2.w * b.w;
            a3 += v3.x * b.x + v3.y * b.y + v3.z * b.z + v3.w * b.w;
        }
#pragma unroll
        for (int o = 16; o > 0; o >>= 1) {
            a0 += __shfl_xor_sync(0xffffffffu, a0, o);
            a1 += __shfl_xor_sync(0xffffffffu, a1, o);
            a2 += __shfl_xor_sync(0xffffffffu, a2, o);
            a3 += __shfl_xor_sync(0xffffffffu, a3, o);
        }
        if (lane == 0) {
            g_bias[row0 + 0] = a0;
            g_bias[row0 + 1] = a1;
            g_bias[row0 + 2] = a2;
            g_bias[row0 + 3] = a3;
        }
        cudaTriggerProgrammaticLaunchCompletion();
        return;
    }

    // ----------------- match path: rare-hit bitmap filter ------------------
    const int b = (bid >> 2) * 3 + (bid & 3);  // 0..2303
    if (b >= NMATCH) {
        cudaTriggerProgrammaticLaunchCompletion();
        return;
    }

#pragma unroll
    for (int r = 0; r < (DICT / 32) / 256; r++)
        s_bm[t + 256 * r] = 0u;

    if (t < KTOP) {
        int ui = up_indices[b * KTOP + t];
        s_up_idx[t]   = ui;
        s_up_val[t]   = up_vals[b * KTOP + t];
        s_down_idx[t] = down_indices[b * KTOP + t];
        out[b * KTOP + t] = 0.f;              // base; everything adds atomically
    }
    __syncthreads();

    if (t < KTOP)
        atomicOr(&s_bm[(unsigned)s_up_idx[t] >> 5], 1u << (s_up_idx[t] & 31));
    __syncthreads();

    // 32 rows x 16 int4 = 512 items streamed through the bitmap.
#pragma unroll
    for (int item = t; item < KTOP * (CONN / 4); item += 256) {
        int i = item >> 4;
        int q = item & 15;
        int di = s_down_idx[i];
        int4 a = reinterpret_cast<const int4*>(connections + (size_t)di * CONN)[q];
        int av[4] = {a.x, a.y, a.z, a.w};
#pragma unroll
        for (int s = 0; s < 4; s++) {
            int v = av[s];
            bool hit = false;
            if (v >= 0)
                hit = (s_bm[(unsigned)v >> 5] >> (v & 31)) & 1u;
            if (hit) {
                // rare (~0.23% of slots): resolve matching j's (handles dups)
                for (int j = 0; j < KTOP; j++) {
                    if (s_up_idx[j] == v) {
                        unsigned pos = atomicAdd(&g_bcnt[(unsigned)v >> 6], 1u);
                        if (pos < CAP) {
                            uint4 rec;
                            rec.x = (unsigned)(b * KTOP + i);
                            rec.y = (unsigned)di;
                            rec.z = (unsigned)v;
                            rec.w = __float_as_uint(s_up_val[j]);
                            g_bpairs[((unsigned)v >> 6) * CAP + pos] = rec;
                        }
                    }
                }
            }
        }
    }
    cudaTriggerProgrammaticLaunchCompletion();
}

// ---------------------------------------------------------------------------
// K2: fused slab dots, software-pipelined, launched via PDL. Slab loads are
// independent of K1 and issue BEFORE cudaGridDependencySynchronize(), so K2's
// DRAM ramp overlaps K1's tail. All K1-dependent reads come after the sync.
// ---------------------------------------------------------------------------
__global__ __launch_bounds__(256) void k2_kernel(
    const float* __restrict__ up_decoder_w,   // [D, DICT]
    const float* __restrict__ down_encoder_w, // [DICT, D]
    const int*   __restrict__ up_indices,     // [B*K]
    float*       __restrict__ out)            // [B*K]
{
    __shared__ float    s[DH * SROW];          // 16,640 B slab
    __shared__ unsigned s_cnt;

    const int bid = blockIdx.x;
    const int t   = threadIdx.x;

    if (bid % 19 == 18) {
        // ----------------- epilogue path: add bias base --------------------
        cudaGridDependencySynchronize();       // g_bias + zeroed out
        int i = (bid / 19) * 256 + t;
        atomicAdd(&out[i], g_bias[up_indices[i]]);
        return;
    }

    // ----------------- fused path ------------------------------------------
    const int fidx  = (bid / 19) * 18 + (bid % 19);  // 0..NFUSE-1
    const int tile  = fidx / NSL;
    const int slice = fidx % NSL;
    const int f0 = tile * FT;
    const int d0 = slice * DH;
    const int warp = t >> 5;
    const int lane = t & 31;

    // (1) Issue slab loads first (independent of K1): 1024 float4, 4/thread.
    const float4* src = reinterpret_cast<const float4*>(
        up_decoder_w + (size_t)d0 * DICT + f0);
    const int RS4 = DICT / 4;
    float4 v0 = __ldcs(&src[(size_t)((t + 0) >> 4) * RS4 + ((t + 0) & 15)]);
    float4 v1 = __ldcs(&src[(size_t)((t + 256) >> 4) * RS4 + ((t + 256) & 15)]);
    float4 v2 = __ldcs(&src[(size_t)((t + 512) >> 4) * RS4 + ((t + 512) & 15)]);
    float4 v3 = __ldcs(&src[(size_t)((t + 768) >> 4) * RS4 + ((t + 768) & 15)]);

    // (2) Wait for K1 (overlapped with the slab DRAM service above).
    cudaGridDependencySynchronize();

    // (3) Dependent reads: count + speculative first record + its drow.
    if (t == 0) s_cnt = g_bcnt[tile];
    uint4 rec0 = g_bpairs[tile * CAP + warp];        // speculative, bounds-safe
    const float* drow0 = down_encoder_w + (size_t)rec0.y * DDIM + d0;
    float dr0a = drow0[lane];
    float dr0b = drow0[lane + 32];

    // (4) Store slab to smem, barrier.
    {
        float* d;
        d = &s[((t + 0) >> 4) * SROW + ((t + 0) & 15) * 4];
        d[0] = v0.x; d[1] = v0.y; d[2] = v0.z; d[3] = v0.w;
        d = &s[((t + 256) >> 4) * SROW + ((t + 256) & 15) * 4];
        d[0] = v1.x; d[1] = v1.y; d[2] = v1.z; d[3] = v1.w;
        d = &s[((t + 512) >> 4) * SROW + ((t + 512) & 15) * 4];
        d[0] = v2.x; d[1] = v2.y; d[2] = v2.z; d[3] = v2.w;
        d = &s[((t + 768) >> 4) * SROW + ((t + 768) & 15) * 4];
        d[0] = v3.x; d[1] = v3.y; d[2] = v3.z; d[3] = v3.w;
    }
    __syncthreads();

    const unsigned cnt_raw = s_cnt;
    // Arrive/reset AFTER the barrier: t0's count value is consumed (in smem),
    // so the last slice-block may safely zero the counters for the next replay.
    if (t == 0) {
        unsigned old = atomicAdd(&g_done[tile], 1u);
        if (old == NSL - 1) {
            g_bcnt[tile] = 0u;
            g_done[tile] = 0u;
        }
    }
    const int cnt = (int)(cnt_raw < CAP ? cnt_raw : CAP);
    if (cnt == 0) return;

    // (5) Record 0: fully prefetched — pure smem + register math.
    if (warp < cnt) {
        const int fl = (int)rec0.z - f0;
        float acc = s[lane * SROW + fl] * dr0a
                  + s[(lane + 32) * SROW + fl] * dr0b;
#pragma unroll
        for (int o = 16; o > 0; o >>= 1)
            acc += __shfl_xor_sync(0xffffffffu, acc, o);
        if (lane == 0)
            atomicAdd(&out[rec0.x], acc * __uint_as_float(rec0.w));
    }

    // Rare extra records (cnt > 8): slow path.
    for (int p = warp + 8; p < cnt; p += 8) {
        uint4 rec = g_bpairs[tile * CAP + p];
        const int fl = (int)rec.z - f0;
        const float* drow = down_encoder_w + (size_t)rec.y * DDIM + d0;
        float acc = s[lane * SROW + fl] * drow[lane]
                  + s[(lane + 32) * SROW + fl] * drow[lane + 32];
#pragma unroll
        for (int o = 16; o > 0; o >>= 1)
            acc += __shfl_xor_sync(0xffffffffu, acc, o);
        if (lane == 0)
            atomicAdd(&out[rec.x], acc * __uint_as_float(rec.w));
    }
}

// ---------------------------------------------------------------------------
extern "C" void kernel_launch(void* const* d_in, const int* in_sizes, int n_in,
                              void* d_out, int out_size)
{
    const float* up_vals        = (const float*)d_in[0];
    const float* up_decoder_w   = (const float*)d_in[1];
    const float* down_encoder_w = (const float*)d_in[2];
    const float* up_encoder_w   = (const float*)d_in[3];
    const float* b_dec          = (const float*)d_in[4];
    const int*   up_indices     = (const int*)d_in[5];
    const int*   down_indices   = (const int*)d_in[6];
    const int*   connections    = (const int*)d_in[7];
    float*       out            = (float*)d_out;

    k1_kernel<<<NK1, 256>>>(up_vals, up_indices, down_indices, connections,
                            up_encoder_w, b_dec, out);

    // K2 via PDL: may begin executing while K1 drains; K2 synchronizes on K1
    // internally before touching K1's outputs.
    cudaLaunchConfig_t cfg = {};
    cfg.gridDim  = dim3(NK2, 1, 1);
    cfg.blockDim = dim3(256, 1, 1);
    cfg.dynamicSmemBytes = 0;
    cfg.stream = 0;
    cudaLaunchAttribute attrs[1];
    attrs[0].id = cudaLaunchAttributeProgrammaticStreamSerialization;
    attrs[0].val.programmaticStreamSerializationAllowed = 1;
    cfg.attrs = attrs;
    cfg.numAttrs = 1;
    cudaLaunchKernelEx(&cfg, k2_kernel,
                       up_decoder_w, down_encoder_w, up_indices, out);
}

// round 15
// speedup vs baseline: 1.2464x; 1.0731x over previous
#include <cuda_runtime.h>
#include <stdint.h>

#define BATCH 2048
#define KTOP  32
#define DDIM  768
#define DICT  24576
#define CONN  64

#define FT    64                 // up-feature tile width
#define NFT   (DICT / FT)        // 384 tiles
#define DH    128                // d-slice size
#define NSL   (DDIM / DH)        // 6 slices
#define CAP   256                // max pair records per tile bucket
#define SROWF 68                 // padded smem row stride in floats (272B = 17*16B)

#define NMATCH 2048
#define NK1    3072              // (bid&3)==3 -> bias (768), else match slot

#define NFUSE  (NSL * NFT)       // 2304
#define NEPI   256
#define NK2    2560              // bid%10==9 -> epilogue (256), else fused (2304)

__device__ float    g_bias[DICT];
__device__ unsigned g_bcnt[NFT];     // zeroed by K2 after use (self-maintaining)
__device__ unsigned g_done[NFT];     // arrival counters, self-resetting
// pair record: x = out position (b*K+i), y = down dict idx, z = up dict idx,
//              w = float bits of up_val[j]   (one record PER HIT)
// NOTE: every field ever written is bounded (x < B*K, y/z < DICT), and the
// array is zero-initialized, so SPECULATIVE reads of stale records are safe.
__device__ uint4    g_bpairs[NFT * CAP];

// ---------------------------------------------------------------------------
// K1: match (latency-bound) co-scheduled with bias matvec (DRAM-bound), 3:1.
// Identical to R14 (measured ~16.5us; at the bias-matvec plateau).
// ---------------------------------------------------------------------------
__global__ __launch_bounds__(256) void k1_kernel(
    const float* __restrict__ up_vals,        // [B, K]
    const int*   __restrict__ up_indices,     // [B, K]
    const int*   __restrict__ down_indices,   // [B, K]
    const int*   __restrict__ connections,    // [DICT, C]
    const float* __restrict__ up_encoder_w,   // [DICT, D]
    const float* __restrict__ b_dec,          // [D]
    float*       __restrict__ out)            // [B, K]
{
    __shared__ float    s_b[DDIM];            // bias path
    __shared__ int      s_up_idx[KTOP];       // match path
    __shared__ float    s_up_val[KTOP];
    __shared__ int      s_down_idx[KTOP];
    __shared__ unsigned s_bm[DICT / 32];      // 3KB presence bitmap

    const int bid  = blockIdx.x;
    const int t    = threadIdx.x;
    const int warp = t >> 5;
    const int lane = t & 31;

    if ((bid & 3) == 3) {
        // ----------------- bias path: 32 rows, 4 per warp (MLP 24) ---------
        for (int i = t; i < DDIM; i += 256) s_b[i] = b_dec[i];
        __syncthreads();

        const int row0 = (bid >> 2) * 32 + warp * 4;
        const float4* w  = reinterpret_cast<const float4*>(
            up_encoder_w + (size_t)row0 * DDIM);
        const float4* bb = reinterpret_cast<const float4*>(s_b);
        const int RS = DDIM / 4;               // 192
        float a0 = 0.f, a1 = 0.f, a2 = 0.f, a3 = 0.f;
#pragma unroll
        for (int k = 0; k < DDIM / 128; k++) { // 6 iters, 24 indep LDG.128
            int c = lane + 32 * k;
            float4 b  = bb[c];
            float4 v0 = __ldcs(&w[0 * RS + c]);   // streaming: no L2 reuse
            float4 v1 = __ldcs(&w[1 * RS + c]);
            float4 v2 = __ldcs(&w[2 * RS + c]);
            float4 v3 = __ldcs(&w[3 * RS + c]);
            a0 += v0.x * b.x + v0.y * b.y + v0.z * b.z + v0.w * b.w;
            a1 += v1.x * b.x + v1.y * b.y + v1.z * b.z + v1.w * b.w;
            a2 += v2.x * b.x + v2.y * b.y + v2.z * b.z + v2.w * b.w;
            a3 += v3.x * b.x + v3.y * b.y + v3.z * b.z + v3.w * b.w;
        }
#pragma unroll
        for (int o = 16; o > 0; o >>= 1) {
            a0 += __shfl_xor_sync(0xffffffffu, a0, o);
            a1 += __shfl_xor_sync(0xffffffffu, a1, o);
            a2 += __shfl_xor_sync(0xffffffffu, a2, o);
            a3 += __shfl_xor_sync(0xffffffffu, a3, o);
        }
        if (lane == 0) {
            g_bias[row0 + 0] = a0;
            g_bias[row0 + 1] = a1;
            g_bias[row0 + 2] = a2;
            g_bias[row0 + 3] = a3;
        }
        cudaTriggerProgrammaticLaunchCompletion();
        return;
    }

    // ----------------- match path: rare-hit bitmap filter ------------------
    const int b = (bid >> 2) * 3 + (bid & 3);  // 0..2303
    if (b >= NMATCH) {
        cudaTriggerProgrammaticLaunchCompletion();
        return;
    }

#pragma unroll
    for (int r = 0; r < (DICT / 32) / 256; r++)
        s_bm[t + 256 * r] = 0u;

    if (t < KTOP) {
        int ui = up_indices[b * KTOP + t];
        s_up_idx[t]   = ui;
        s_up_val[t]   = up_vals[b * KTOP + t];
        s_down_idx[t] = down_indices[b * KTOP + t];
        out[b * KTOP + t] = 0.f;              // base; everything adds atomically
    }
    __syncthreads();

    if (t < KTOP)
        atomicOr(&s_bm[(unsigned)s_up_idx[t] >> 5], 1u << (s_up_idx[t] & 31));
    __syncthreads();

    // 32 rows x 16 int4 = 512 items streamed through the bitmap.
#pragma unroll
    for (int item = t; item < KTOP * (CONN / 4); item += 256) {
        int i = item >> 4;
        int q = item & 15;
        int di = s_down_idx[i];
        int4 a = reinterpret_cast<const int4*>(connections + (size_t)di * CONN)[q];
        int av[4] = {a.x, a.y, a.z, a.w};
#pragma unroll
        for (int s = 0; s < 4; s++) {
            int v = av[s];
            bool hit = false;
            if (v >= 0)
                hit = (s_bm[(unsigned)v >> 5] >> (v & 31)) & 1u;
            if (hit) {
                // rare (~0.23% of slots): resolve matching j's (handles dups)
                for (int j = 0; j < KTOP; j++) {
                    if (s_up_idx[j] == v) {
                        unsigned pos = atomicAdd(&g_bcnt[(unsigned)v >> 6], 1u);
                        if (pos < CAP) {
                            uint4 rec;
                            rec.x = (unsigned)(b * KTOP + i);
                            rec.y = (unsigned)di;
                            rec.z = (unsigned)v;
                            rec.w = __float_as_uint(s_up_val[j]);
                            g_bpairs[((unsigned)v >> 6) * CAP + pos] = rec;
                        }
                    }
                }
            }
        }
    }
    cudaTriggerProgrammaticLaunchCompletion();
}

// ---------------------------------------------------------------------------
// K2: cp.async-fed slab dots (L2->smem direct, no L1/register staging),
// DH=128 (8 cp.async/thread), PDL-launched, two records/warp prefetched.
// ---------------------------------------------------------------------------
__global__ __launch_bounds__(256) void k2_kernel(
    const float* __restrict__ up_decoder_w,   // [D, DICT]
    const float* __restrict__ down_encoder_w, // [DICT, D]
    const int*   __restrict__ up_indices,     // [B*K]
    float*       __restrict__ out)            // [B*K]
{
    __shared__ float    s[DH * SROWF];         // 34,816 B slab (16B-aligned rows)
    __shared__ unsigned s_cnt;

    const int bid = blockIdx.x;
    const int t   = threadIdx.x;

    if (bid % 10 == 9) {
        // ----------------- epilogue path: add bias base --------------------
        int i  = (bid / 10) * 256 + t;
        int ui = up_indices[i];                // independent of K1: before sync
        cudaGridDependencySynchronize();       // g_bias + zeroed out
        atomicAdd(&out[i], g_bias[ui]);
        return;
    }

    // ----------------- fused path ------------------------------------------
    const int fidx  = (bid / 10) * 9 + (bid % 10);   // 0..NFUSE-1
    const int tile  = fidx / NSL;
    const int slice = fidx % NSL;
    const int f0 = tile * FT;
    const int d0 = slice * DH;
    const int warp = t >> 5;
    const int lane = t & 31;

    // (1) Slab fill via cp.async.cg: DH x FT floats = 2048 x 16B chunks,
    //     8 per thread, gmem -> smem direct (bypasses L1 + registers).
    {
        const char* gbase = reinterpret_cast<const char*>(
            up_decoder_w + (size_t)d0 * DICT + f0);
#pragma unroll
        for (int it = 0; it < 8; it++) {
            int idx = t + 256 * it;
            int row = idx >> 4;                // 16 chunks per row
            int c4  = idx & 15;
            unsigned saddr = (unsigned)__cvta_generic_to_shared(
                &s[row * SROWF]) + c4 * 16;
            const char* gaddr = gbase + (size_t)row * (DICT * 4) + c4 * 16;
            asm volatile("cp.async.cg.shared.global [%0], [%1], 16;"
                         :: "r"(saddr), "l"(gaddr));
        }
        asm volatile("cp.async.commit_group;");
    }

    // (2) Wait for K1 (slab copies already streaming in the background).
    cudaGridDependencySynchronize();

    // (3) Dependent reads: count + two speculative records + their drows.
    if (t == 0) s_cnt = g_bcnt[tile];
    uint4 rec0 = g_bpairs[tile * CAP + warp];          // speculative, safe
    uint4 rec1 = g_bpairs[tile * CAP + warp + 8];      // speculative, safe
    const float* drow0 = down_encoder_w + (size_t)rec0.y * DDIM + d0;
    const float* drow1 = down_encoder_w + (size_t)rec1.y * DDIM + d0;
    float d0a = drow0[lane],      d0b = drow0[lane + 32];
    float d0c = drow0[lane + 64], d0d = drow0[lane + 96];
    float d1a = drow1[lane],      d1b = drow1[lane + 32];
    float d1c = drow1[lane + 64], d1d = drow1[lane + 96];

    // (4) Drain slab copies, barrier.
    asm volatile("cp.async.wait_group 0;");
    __syncthreads();

    const unsigned cnt_raw = s_cnt;
    // Arrive/reset AFTER the barrier: t0's count value is consumed (in smem),
    // so the last slice-block may safely zero the counters for the next replay.
    if (t == 0) {
        unsigned old = atomicAdd(&g_done[tile], 1u);
        if (old == NSL - 1) {
            g_bcnt[tile] = 0u;
            g_done[tile] = 0u;
        }
    }
    const int cnt = (int)(cnt_raw < CAP ? cnt_raw : CAP);
    if (cnt == 0) return;

    // (5) Prefetched records: pure smem + register math.
    if (warp < cnt) {
        const int fl = (int)rec0.z - f0;
        float acc = s[(lane +  0) * SROWF + fl] * d0a
                  + s[(lane + 32) * SROWF + fl] * d0b
                  + s[(lane + 64) * SROWF + fl] * d0c
                  + s[(lane + 96) * SROWF + fl] * d0d;
#pragma unroll
        for (int o = 16; o > 0; o >>= 1)
            acc += __shfl_xor_sync(0xffffffffu, acc, o);
        if (lane == 0)
            atomicAdd(&out[rec0.x], acc * __uint_as_float(rec0.w));
    }
    if (warp + 8 < cnt) {
        const int fl = (int)rec1.z - f0;
        float acc = s[(lane +  0) * SROWF + fl] * d1a
                  + s[(lane + 32) * SROWF + fl] * d1b
                  + s[(lane + 64) * SROWF + fl] * d1c
                  + s[(lane + 96) * SROWF + fl] * d1d;
#pragma unroll
        for (int o = 16; o > 0; o >>= 1)
            acc += __shfl_xor_sync(0xffffffffu, acc, o);
        if (lane == 0)
            atomicAdd(&out[rec1.x], acc * __uint_as_float(rec1.w));
    }

    // Rare extra records (cnt > 16): slow path.
    for (int p = warp + 16; p < cnt; p += 8) {
        uint4 rec = g_bpairs[tile * CAP + p];
        const int fl = (int)rec.z - f0;
        const float* drow = down_encoder_w + (size_t)rec.y * DDIM + d0;
        float acc = s[(lane +  0) * SROWF + fl] * drow[lane]
                  + s[(lane + 32) * SROWF + fl] * drow[lane + 32]
                  + s[(lane + 64) * SROWF + fl] * drow[lane + 64]
                  + s[(lane + 96) * SROWF + fl] * drow[lane + 96];
#pragma unroll
        for (int o = 16; o > 0; o >>= 1)
            acc += __shfl_xor_sync(0xffffffffu, acc, o);
        if (lane == 0)
            atomicAdd(&out[rec.x], acc * __uint_as_float(rec.w));
    }
}

// ---------------------------------------------------------------------------
extern "C" void kernel_launch(void* const* d_in, const int* in_sizes, int n_in,
                              void* d_out, int out_size)
{
    const float* up_vals        = (const float*)d_in[0];
    const float* up_decoder_w   = (const float*)d_in[1];
    const float* down_encoder_w = (const float*)d_in[2];
    const float* up_encoder_w   = (const float*)d_in[3];
    const float* b_dec          = (const float*)d_in[4];
    const int*   up_indices     = (const int*)d_in[5];
    const int*   down_indices   = (const int*)d_in[6];
    const int*   connections    = (const int*)d_in[7];
    float*       out            = (float*)d_out;

    k1_kernel<<<NK1, 256>>>(up_vals, up_indices, down_indices, connections,
                            up_encoder_w, b_dec, out);

    // K2 via PDL: may begin executing while K1 drains; K2 synchronizes on K1
    // internally before touching K1's outputs.
    cudaLaunchConfig_t cfg = {};
    cfg.gridDim  = dim3(NK2, 1, 1);
    cfg.blockDim = dim3(256, 1, 1);
    cfg.dynamicSmemBytes = 0;
    cfg.stream = 0;
    cudaLaunchAttribute attrs[1];
    attrs[0].id = cudaLaunchAttributeProgrammaticStreamSerialization;
    attrs[0].val.programmaticStreamSerializationAllowed = 1;
    cfg.attrs = attrs;
    cfg.numAttrs = 1;
    cudaLaunchKernelEx(&cfg, k2_kernel,
                       up_decoder_w, down_encoder_w, up_indices, out);
}